// round 4
// baseline (speedup 1.0000x reference)
#include <cuda_runtime.h>
#include <math.h>

#define B_   4
#define HWC  4096    // 64*64
#define HWF  16384   // 128*128

// ---------------- scratch (static device allocations; no cudaMalloc) -------
__device__ float g_warp[B_ * 2 * HWC];
__device__ float g_xin [B_ * 130 * HWC];
__device__ float g_za  [B_ * 256 * HWC];    // == B_*64*HWF, reused for fine net
__device__ float g_zb  [B_ * 256 * HWC];
__device__ float g_up  [B_ * 3 * HWF];
__device__ float g_yin [B_ * 50 * HWF];
__device__ float g_ps  [256 * 512];
__device__ float g_pq  [256 * 512];
__device__ float g_scale[256];
__device__ float g_shift[256];

// ---------------------------------------------------------------------------
// Kernel 1: fused correlation GEMM + online softmax + expectation over grid.
// Per batch: corr[p,j] = (1/8) * sum_c f0[c,p] * f1[c,j]; warp = softmax_j(corr) @ g
// Tile: M=32 pixels per block, N=128 j per iteration, K=64 (full).
// ---------------------------------------------------------------------------
__global__ __launch_bounds__(256) void corr_warp_kernel(
    const float* __restrict__ f0, const float* __restrict__ f1,
    float* __restrict__ warp)
{
    __shared__ __align__(16) float As[64][32];
    __shared__ __align__(16) float Bs[64][128];

    const int b  = blockIdx.y;
    const int p0 = blockIdx.x * 32;
    const int tid = threadIdx.x;
    const int tn = tid & 31;        // lane: 4 j-columns each
    const int tm = tid >> 5;        // warp: 4 pixel rows each

    const float* f0b = f0 + b * 64 * HWC;
    const float* f1b = f1 + b * 64 * HWC;

    for (int e = tid; e < 64 * 32; e += 256) {
        int c = e >> 5, p = e & 31;
        As[c][p] = f0b[c * HWC + p0 + p];
    }

    float m[4], s[4], sx[4], sy[4];
#pragma unroll
    for (int r = 0; r < 4; r++) { m[r] = -INFINITY; s[r] = 0.f; sx[r] = 0.f; sy[r] = 0.f; }

    for (int j0 = 0; j0 < HWC; j0 += 128) {
        __syncthreads();
        for (int e = tid; e < 64 * 128; e += 256) {
            int c = e >> 7, j = e & 127;
            Bs[c][j] = f1b[c * HWC + j0 + j];
        }
        __syncthreads();

        float acc[4][4];
#pragma unroll
        for (int r = 0; r < 4; r++)
#pragma unroll
            for (int u = 0; u < 4; u++) acc[r][u] = 0.f;

#pragma unroll 8
        for (int c = 0; c < 64; c++) {
            float4 a  = *(const float4*)&As[c][tm * 4];
            float4 bv = *(const float4*)&Bs[c][tn * 4];
            acc[0][0] = fmaf(a.x, bv.x, acc[0][0]); acc[0][1] = fmaf(a.x, bv.y, acc[0][1]);
            acc[0][2] = fmaf(a.x, bv.z, acc[0][2]); acc[0][3] = fmaf(a.x, bv.w, acc[0][3]);
            acc[1][0] = fmaf(a.y, bv.x, acc[1][0]); acc[1][1] = fmaf(a.y, bv.y, acc[1][1]);
            acc[1][2] = fmaf(a.y, bv.z, acc[1][2]); acc[1][3] = fmaf(a.y, bv.w, acc[1][3]);
            acc[2][0] = fmaf(a.z, bv.x, acc[2][0]); acc[2][1] = fmaf(a.z, bv.y, acc[2][1]);
            acc[2][2] = fmaf(a.z, bv.z, acc[2][2]); acc[2][3] = fmaf(a.z, bv.w, acc[2][3]);
            acc[3][0] = fmaf(a.w, bv.x, acc[3][0]); acc[3][1] = fmaf(a.w, bv.y, acc[3][1]);
            acc[3][2] = fmaf(a.w, bv.z, acc[3][2]); acc[3][3] = fmaf(a.w, bv.w, acc[3][3]);
        }

        // online softmax update per pixel row (reduce across the 32 lanes of a warp)
#pragma unroll
        for (int r = 0; r < 4; r++) {
            float v[4];
#pragma unroll
            for (int u = 0; u < 4; u++) v[u] = acc[r][u] * 0.125f;
            float lm = fmaxf(fmaxf(v[0], v[1]), fmaxf(v[2], v[3]));
#pragma unroll
            for (int o = 16; o > 0; o >>= 1)
                lm = fmaxf(lm, __shfl_xor_sync(0xffffffffu, lm, o));
            float nm = fmaxf(m[r], lm);

            float ls = 0.f, lx = 0.f, ly = 0.f;
            int jb = j0 + tn * 4;
#pragma unroll
            for (int u = 0; u < 4; u++) {
                int j = jb + u;
                float e = __expf(v[u] - nm);
                float gx = (float)(2 * (j & 63) - 63) * (1.f / 64.f);
                float gy = (float)(2 * (j >> 6) - 63) * (1.f / 64.f);
                ls += e; lx = fmaf(e, gx, lx); ly = fmaf(e, gy, ly);
            }
#pragma unroll
            for (int o = 16; o > 0; o >>= 1) {
                ls += __shfl_xor_sync(0xffffffffu, ls, o);
                lx += __shfl_xor_sync(0xffffffffu, lx, o);
                ly += __shfl_xor_sync(0xffffffffu, ly, o);
            }
            float sc = __expf(m[r] - nm);
            s[r]  = s[r]  * sc + ls;
            sx[r] = sx[r] * sc + lx;
            sy[r] = sy[r] * sc + ly;
            m[r]  = nm;
        }
    }

    if (tn == 0) {
#pragma unroll
        for (int r = 0; r < 4; r++) {
            int p = p0 + tm * 4 + r;
            warp[(b * 2 + 0) * HWC + p] = sx[r] / s[r];
            warp[(b * 2 + 1) * HWC + p] = sy[r] / s[r];
        }
    }
}

// ---------------------------------------------------------------------------
// Kernel 2: grid-sample feats1 at warp + concat [feats0 | warped1 | warp]
// out channels = 2C+2.  warp layout: [b][0][HW],[b][1][HW] with batch stride.
// ---------------------------------------------------------------------------
__global__ void sample_concat_kernel(
    const float* __restrict__ f0, const float* __restrict__ f1,
    const float* __restrict__ warp, int warp_bstride,
    float* __restrict__ out, int C, int H, int W)
{
    int idx = blockIdx.x * blockDim.x + threadIdx.x;
    int HW = H * W;
    if (idx >= B_ * HW) return;
    int b = idx / HW, p = idx - b * HW;

    float wx = warp[b * warp_bstride + p];
    float wy = warp[b * warp_bstride + HW + p];
    float x = (wx + 1.f) * (W * 0.5f) - 0.5f;
    float y = (wy + 1.f) * (H * 0.5f) - 0.5f;
    float x0f = floorf(x), y0f = floorf(y);
    float fx = x - x0f, fy = y - y0f;
    int x0 = (int)x0f, y0 = (int)y0f;
    int x1 = x0 + 1, y1 = y0 + 1;
    bool vx0 = (x0 >= 0 && x0 < W), vx1 = (x1 >= 0 && x1 < W);
    bool vy0 = (y0 >= 0 && y0 < H), vy1 = (y1 >= 0 && y1 < H);
    float w00 = (vx0 && vy0) ? (1.f - fx) * (1.f - fy) : 0.f;
    float w01 = (vx1 && vy0) ? fx * (1.f - fy) : 0.f;
    float w10 = (vx0 && vy1) ? (1.f - fx) * fy : 0.f;
    float w11 = (vx1 && vy1) ? fx * fy : 0.f;
    int x0c = min(max(x0, 0), W - 1), x1c = min(max(x1, 0), W - 1);
    int y0c = min(max(y0, 0), H - 1), y1c = min(max(y1, 0), H - 1);
    int i00 = y0c * W + x0c, i01 = y0c * W + x1c;
    int i10 = y1c * W + x0c, i11 = y1c * W + x1c;

    const float* f0b = f0 + (long)b * C * HW;
    const float* f1b = f1 + (long)b * C * HW;
    int outC = 2 * C + 2;
    float* ob = out + (long)b * outC * HW;

    for (int c = 0; c < C; c++) {
        const float* pl = f1b + c * HW;
        float v = w00 * pl[i00] + w01 * pl[i01] + w10 * pl[i10] + w11 * pl[i11];
        ob[(C + c) * HW + p] = v;
        ob[c * HW + p] = f0b[c * HW + p];
    }
    ob[(2 * C) * HW + p]     = wx;
    ob[(2 * C + 1) * HW + p] = wy;
}

// ---------------------------------------------------------------------------
// Kernel 3: direct 3x3 SAME conv, NCHW, fp32.
//  - input BN(scale,shift)+ReLU applied on the fly during smem load (or identity)
//  - per-block deterministic partial sum/sumsq per channel for next BN
//  Block: 64 output channels x 1 row x full width.  256 thr = 16 co-grp x 16 w-grp.
//  Thread micro-tile: 4 co x (W/16) w.  Weights staged as [ci][k][co] for LDS.128.
// ---------------------------------------------------------------------------
template <int W_>
__global__ __launch_bounds__(256) void conv3x3_kernel(
    const float* __restrict__ in, const float* __restrict__ wgt,
    const float* __restrict__ bnscale, const float* __restrict__ bnshift,
    float* __restrict__ out, float* __restrict__ psum, float* __restrict__ psq,
    int CI, int CO, int H)
{
    const int WPT = W_ / 16;
    __shared__ float in_s[4][3][W_ + 2];
    __shared__ __align__(16) float wt_s[4][9][64];
    __shared__ float2 red[64][17];

    const int cob = blockIdx.x * 64;
    const int h   = blockIdx.y;
    const int b   = blockIdx.z;
    const int tid = threadIdx.x;
    const int cog = tid >> 4;
    const int wg  = tid & 15;

    // weight-stage mapping: one (ci,co) pair per thread, 9 contiguous gmem floats
    const int w_ci = tid >> 6;      // 0..3
    const int w_co = tid & 63;      // 0..63

    float acc[4][WPT];
#pragma unroll
    for (int i = 0; i < 4; i++)
#pragma unroll
        for (int u = 0; u < WPT; u++) acc[i][u] = 0.f;

    const int nch = (CI + 3) >> 2;
    for (int ch = 0; ch < nch; ch++) {
        const int ci0 = ch * 4;
        __syncthreads();
        const int RW = W_ + 2;
        for (int e = tid; e < 4 * 3 * RW; e += 256) {
            int ci = e / (3 * RW);
            int rem = e - ci * (3 * RW);
            int r = rem / RW;
            int colp = rem - r * RW;
            int col = colp - 1;
            int row = h + r - 1;
            int cig = ci0 + ci;
            float v = 0.f;
            if (cig < CI && (unsigned)row < (unsigned)H && (unsigned)col < (unsigned)W_) {
                v = in[(((long)b * CI + cig) * H + row) * W_ + col];
                if (bnscale) v = fmaxf(fmaf(v, bnscale[cig], bnshift[cig]), 0.f);
            }
            in_s[ci][r][colp] = v;
        }
        {
            int cig = ci0 + w_ci;
            if (cig < CI) {
                const float* wp = wgt + (((long)(cob + w_co)) * CI + cig) * 9;
#pragma unroll
                for (int k = 0; k < 9; k++) wt_s[w_ci][k][w_co] = wp[k];
            } else {
#pragma unroll
                for (int k = 0; k < 9; k++) wt_s[w_ci][k][w_co] = 0.f;
            }
        }
        __syncthreads();

#pragma unroll
        for (int ci = 0; ci < 4; ci++) {
            float xr[3][WPT + 2];
#pragma unroll
            for (int r = 0; r < 3; r++)
#pragma unroll
                for (int u = 0; u < WPT + 2; u++)
                    xr[r][u] = in_s[ci][r][wg * WPT + u];
#pragma unroll
            for (int k = 0; k < 9; k++) {
                const int kh = k / 3, kw = k - kh * 3;
                float4 wv = *(const float4*)&wt_s[ci][k][cog * 4];
#pragma unroll
                for (int u = 0; u < WPT; u++) {
                    float xv = xr[kh][u + kw];
                    acc[0][u] = fmaf(wv.x, xv, acc[0][u]);
                    acc[1][u] = fmaf(wv.y, xv, acc[1][u]);
                    acc[2][u] = fmaf(wv.z, xv, acc[2][u]);
                    acc[3][u] = fmaf(wv.w, xv, acc[3][u]);
                }
            }
        }
    }

#pragma unroll
    for (int i = 0; i < 4; i++) {
        int co = cob + cog * 4 + i;
        float* op = out + (((long)b * CO + co) * H + h) * W_ + wg * WPT;
#pragma unroll
        for (int u = 0; u < WPT; u++) op[u] = acc[i][u];
    }

    if (psum) {
        const int NB  = gridDim.z * H;
        const int blk = b * H + h;
        __syncthreads();
#pragma unroll
        for (int i = 0; i < 4; i++) {
            float sv = 0.f, sq = 0.f;
#pragma unroll
            for (int u = 0; u < WPT; u++) {
                sv += acc[i][u];
                sq = fmaf(acc[i][u], acc[i][u], sq);
            }
            red[cog * 4 + i][wg] = make_float2(sv, sq);
        }
        __syncthreads();
        if (tid < 64) {
            float sv = 0.f, sq = 0.f;
            for (int w = 0; w < 16; w++) { sv += red[tid][w].x; sq += red[tid][w].y; }
            psum[(cob + tid) * NB + blk] = sv;
            psq [(cob + tid) * NB + blk] = sq;
        }
    }
}

// ---------------------------------------------------------------------------
// BN finalize: one block per channel, 256-thread deterministic tree reduction.
// ---------------------------------------------------------------------------
__global__ __launch_bounds__(256) void bn_finalize_kernel(
    const float* __restrict__ psum, const float* __restrict__ psq,
    float* __restrict__ scale, float* __restrict__ shift,
    int NB, float invN)
{
    __shared__ float ss[256], qq[256];
    const int co  = blockIdx.x;
    const int tid = threadIdx.x;
    float s = 0.f, q = 0.f;
    for (int i = tid; i < NB; i += 256) {
        s += psum[co * NB + i];
        q += psq [co * NB + i];
    }
    ss[tid] = s; qq[tid] = q;
    __syncthreads();
#pragma unroll
    for (int o = 128; o > 0; o >>= 1) {
        if (tid < o) { ss[tid] += ss[tid + o]; qq[tid] += qq[tid + o]; }
        __syncthreads();
    }
    if (tid == 0) {
        float mn  = ss[0] * invN;
        float var = fmaxf(qq[0] * invN - mn * mn, 0.f);
        float rstd = rsqrtf(var + 1e-5f);
        scale[co] = rstd;
        shift[co] = -mn * rstd;
    }
}

// ---------------------------------------------------------------------------
// 1x1 head: out = base + b5 + W5 @ relu(bn(z)).  base_ch channels of base used.
// ---------------------------------------------------------------------------
__global__ __launch_bounds__(256) void head1x1_kernel(
    const float* __restrict__ z, const float* __restrict__ scale,
    const float* __restrict__ shift, const float* __restrict__ w5,
    const float* __restrict__ b5, const float* __restrict__ base,
    int base_ch, int base_bstride, float* __restrict__ out, int CI, int HW)
{
    __shared__ float ws[3 * 256];
    __shared__ float sc[256], sh[256];
    int tid = threadIdx.x;
    for (int e = tid; e < 3 * CI; e += 256) ws[e] = w5[e];
    for (int e = tid; e < CI; e += 256) { sc[e] = scale[e]; sh[e] = shift[e]; }
    __syncthreads();

    int idx = blockIdx.x * 256 + tid;
    if (idx >= B_ * HW) return;
    int b = idx / HW, p = idx - b * HW;

    float a0 = b5[0], a1 = b5[1], a2 = b5[2];
    const float* zb = z + (long)b * CI * HW + p;
    for (int ci = 0; ci < CI; ci++) {
        float v = fmaxf(fmaf(zb[(long)ci * HW], sc[ci], sh[ci]), 0.f);
        a0 = fmaf(ws[ci], v, a0);
        a1 = fmaf(ws[CI + ci], v, a1);
        a2 = fmaf(ws[2 * CI + ci], v, a2);
    }
    const float* bb = base + (long)b * base_bstride;
    out[((long)b * 3 + 0) * HW + p] = a0 + bb[p];
    out[((long)b * 3 + 1) * HW + p] = a1 + bb[HW + p];
    out[((long)b * 3 + 2) * HW + p] = a2 + (base_ch > 2 ? bb[2 * HW + p] : 0.f);
}

// ---------------------------------------------------------------------------
// jax bilinear 2x upsample 64->128 (half-pixel centers, edge-renorm == clamp)
// ---------------------------------------------------------------------------
__global__ void upsample_kernel(const float* __restrict__ cm, float* __restrict__ up)
{
    int idx = blockIdx.x * blockDim.x + threadIdx.x;
    if (idx >= B_ * 3 * HWF) return;
    int wo = idx & 127;
    int ho = (idx >> 7) & 127;
    int cb = idx >> 14;   // b*3 + c
    float fx = wo * 0.5f - 0.25f;
    float fy = ho * 0.5f - 0.25f;
    float x0f = floorf(fx), y0f = floorf(fy);
    float tx = fx - x0f, ty = fy - y0f;
    int x0 = (int)x0f, y0 = (int)y0f;
    int x0c = max(x0, 0), x1c = min(x0 + 1, 63);
    int y0c = max(y0, 0), y1c = min(y0 + 1, 63);
    const float* pl = cm + (long)cb * HWC;
    float v = (1.f - tx) * (1.f - ty) * pl[y0c * 64 + x0c]
            + tx * (1.f - ty) * pl[y0c * 64 + x1c]
            + (1.f - tx) * ty * pl[y1c * 64 + x0c]
            + tx * ty * pl[y1c * 64 + x1c];
    up[idx] = v;
}

// ---------------------------------------------------------------------------
extern "C" void kernel_launch(void* const* d_in, const int* in_sizes, int n_in,
                              void* d_out, int out_size)
{
    const float* f0c = (const float*)d_in[0];
    const float* f1c = (const float*)d_in[1];
    const float* f0f = (const float*)d_in[2];
    const float* f1f = (const float*)d_in[3];
    const float* cw1 = (const float*)d_in[4];
    const float* cw2 = (const float*)d_in[5];
    const float* cw3 = (const float*)d_in[6];
    const float* cw4 = (const float*)d_in[7];
    const float* cw5 = (const float*)d_in[8];
    const float* cb5 = (const float*)d_in[9];
    const float* fw1 = (const float*)d_in[10];
    const float* fw2 = (const float*)d_in[11];
    const float* fw3 = (const float*)d_in[12];
    const float* fw4 = (const float*)d_in[13];
    const float* fw5 = (const float*)d_in[14];
    const float* fb5 = (const float*)d_in[15];
    float* out = (float*)d_out;

    float *warp, *xin, *za, *zb, *up, *yin, *ps, *pq, *scale, *shift;
    cudaGetSymbolAddress((void**)&warp,  g_warp);
    cudaGetSymbolAddress((void**)&xin,   g_xin);
    cudaGetSymbolAddress((void**)&za,    g_za);
    cudaGetSymbolAddress((void**)&zb,    g_zb);
    cudaGetSymbolAddress((void**)&up,    g_up);
    cudaGetSymbolAddress((void**)&yin,   g_yin);
    cudaGetSymbolAddress((void**)&ps,    g_ps);
    cudaGetSymbolAddress((void**)&pq,    g_pq);
    cudaGetSymbolAddress((void**)&scale, g_scale);
    cudaGetSymbolAddress((void**)&shift, g_shift);

    // ---- coarse stage ----
    corr_warp_kernel<<<dim3(HWC / 32, B_), 256>>>(f0c, f1c, warp);
    sample_concat_kernel<<<(B_ * HWC + 255) / 256, 256>>>(f0c, f1c, warp, 2 * HWC,
                                                          xin, 64, 64, 64);
    const float invNc = 1.f / (B_ * HWC);
    conv3x3_kernel<64><<<dim3(4, 64, B_), 256>>>(xin, cw1, nullptr, nullptr,
                                                 za, ps, pq, 130, 256, 64);
    bn_finalize_kernel<<<256, 256>>>(ps, pq, scale, shift, B_ * 64, invNc);
    conv3x3_kernel<64><<<dim3(4, 64, B_), 256>>>(za, cw2, scale, shift,
                                                 zb, ps, pq, 256, 256, 64);
    bn_finalize_kernel<<<256, 256>>>(ps, pq, scale, shift, B_ * 64, invNc);
    conv3x3_kernel<64><<<dim3(4, 64, B_), 256>>>(zb, cw3, scale, shift,
                                                 za, ps, pq, 256, 256, 64);
    bn_finalize_kernel<<<256, 256>>>(ps, pq, scale, shift, B_ * 64, invNc);
    conv3x3_kernel<64><<<dim3(4, 64, B_), 256>>>(za, cw4, scale, shift,
                                                 zb, ps, pq, 256, 256, 64);
    bn_finalize_kernel<<<256, 256>>>(ps, pq, scale, shift, B_ * 64, invNc);
    head1x1_kernel<<<(B_ * HWC + 255) / 256, 256>>>(zb, scale, shift, cw5, cb5,
                                                    warp, 2, 2 * HWC, out, 256, HWC);

    // ---- upsample + fine stage ----
    upsample_kernel<<<(B_ * 3 * HWF + 255) / 256, 256>>>(out, up);
    sample_concat_kernel<<<(B_ * HWF + 255) / 256, 256>>>(f0f, f1f, up, 3 * HWF,
                                                          yin, 24, 128, 128);
    const float invNf = 1.f / (B_ * HWF);
    conv3x3_kernel<128><<<dim3(1, 128, B_), 256>>>(yin, fw1, nullptr, nullptr,
                                                   za, ps, pq, 50, 64, 128);
    bn_finalize_kernel<<<64, 256>>>(ps, pq, scale, shift, B_ * 128, invNf);
    conv3x3_kernel<128><<<dim3(1, 128, B_), 256>>>(za, fw2, scale, shift,
                                                   zb, ps, pq, 64, 64, 128);
    bn_finalize_kernel<<<64, 256>>>(ps, pq, scale, shift, B_ * 128, invNf);
    conv3x3_kernel<128><<<dim3(1, 128, B_), 256>>>(zb, fw3, scale, shift,
                                                   za, ps, pq, 64, 64, 128);
    bn_finalize_kernel<<<64, 256>>>(ps, pq, scale, shift, B_ * 128, invNf);
    conv3x3_kernel<128><<<dim3(1, 128, B_), 256>>>(za, fw4, scale, shift,
                                                   zb, ps, pq, 64, 64, 128);
    bn_finalize_kernel<<<64, 256>>>(ps, pq, scale, shift, B_ * 128, invNf);
    head1x1_kernel<<<(B_ * HWF + 255) / 256, 256>>>(zb, scale, shift, fw5, fb5,
                                                    up, 3, 3 * HWF,
                                                    out + B_ * 3 * HWC, 64, HWF);
}

// round 5
// speedup vs baseline: 1.0012x; 1.0012x over previous
#include <cuda_runtime.h>
#include <math.h>

#define B_   4
#define HWC  4096    // 64*64
#define HWF  16384   // 128*128

// ---------------- scratch (static device allocations; no cudaMalloc) -------
__device__ float g_warp[B_ * 2 * HWC];
__device__ float g_xin [B_ * 130 * HWC];
__device__ float g_za  [B_ * 256 * HWC];    // == B_*64*HWF, reused for fine net
__device__ float g_zb  [B_ * 256 * HWC];
__device__ float g_up  [B_ * 3 * HWF];
__device__ float g_yin [B_ * 50 * HWF];
__device__ float g_ps  [256 * 512];
__device__ float g_pq  [256 * 512];
__device__ float g_scale[256];
__device__ float g_shift[256];

// ---------------------------------------------------------------------------
// Kernel 1: fused correlation GEMM + online softmax + expectation over grid.
// Per batch: corr[p,j] = (1/8) * sum_c f0[c,p] * f1[c,j]; warp = softmax_j(corr) @ g
// Tile: M=32 pixels per block, N=128 j per iteration, K=64 (full).
// ---------------------------------------------------------------------------
__global__ __launch_bounds__(256) void corr_warp_kernel(
    const float* __restrict__ f0, const float* __restrict__ f1,
    float* __restrict__ warp)
{
    __shared__ __align__(16) float As[64][32];
    __shared__ __align__(16) float Bs[64][128];

    const int b  = blockIdx.y;
    const int p0 = blockIdx.x * 32;
    const int tid = threadIdx.x;
    const int tn = tid & 31;        // lane: 4 j-columns each
    const int tm = tid >> 5;        // warp: 4 pixel rows each

    const float* f0b = f0 + b * 64 * HWC;
    const float* f1b = f1 + b * 64 * HWC;

    for (int e = tid; e < 64 * 32; e += 256) {
        int c = e >> 5, p = e & 31;
        As[c][p] = f0b[c * HWC + p0 + p];
    }

    float m[4], s[4], sx[4], sy[4];
#pragma unroll
    for (int r = 0; r < 4; r++) { m[r] = -INFINITY; s[r] = 0.f; sx[r] = 0.f; sy[r] = 0.f; }

    for (int j0 = 0; j0 < HWC; j0 += 128) {
        __syncthreads();
        for (int e = tid; e < 64 * 128; e += 256) {
            int c = e >> 7, j = e & 127;
            Bs[c][j] = f1b[c * HWC + j0 + j];
        }
        __syncthreads();

        float acc[4][4];
#pragma unroll
        for (int r = 0; r < 4; r++)
#pragma unroll
            for (int u = 0; u < 4; u++) acc[r][u] = 0.f;

#pragma unroll 8
        for (int c = 0; c < 64; c++) {
            float4 a  = *(const float4*)&As[c][tm * 4];
            float4 bv = *(const float4*)&Bs[c][tn * 4];
            acc[0][0] = fmaf(a.x, bv.x, acc[0][0]); acc[0][1] = fmaf(a.x, bv.y, acc[0][1]);
            acc[0][2] = fmaf(a.x, bv.z, acc[0][2]); acc[0][3] = fmaf(a.x, bv.w, acc[0][3]);
            acc[1][0] = fmaf(a.y, bv.x, acc[1][0]); acc[1][1] = fmaf(a.y, bv.y, acc[1][1]);
            acc[1][2] = fmaf(a.y, bv.z, acc[1][2]); acc[1][3] = fmaf(a.y, bv.w, acc[1][3]);
            acc[2][0] = fmaf(a.z, bv.x, acc[2][0]); acc[2][1] = fmaf(a.z, bv.y, acc[2][1]);
            acc[2][2] = fmaf(a.z, bv.z, acc[2][2]); acc[2][3] = fmaf(a.z, bv.w, acc[2][3]);
            acc[3][0] = fmaf(a.w, bv.x, acc[3][0]); acc[3][1] = fmaf(a.w, bv.y, acc[3][1]);
            acc[3][2] = fmaf(a.w, bv.z, acc[3][2]); acc[3][3] = fmaf(a.w, bv.w, acc[3][3]);
        }

        // online softmax update per pixel row (reduce across the 32 lanes of a warp)
#pragma unroll
        for (int r = 0; r < 4; r++) {
            float v[4];
#pragma unroll
            for (int u = 0; u < 4; u++) v[u] = acc[r][u] * 0.125f;
            float lm = fmaxf(fmaxf(v[0], v[1]), fmaxf(v[2], v[3]));
#pragma unroll
            for (int o = 16; o > 0; o >>= 1)
                lm = fmaxf(lm, __shfl_xor_sync(0xffffffffu, lm, o));
            float nm = fmaxf(m[r], lm);

            float ls = 0.f, lx = 0.f, ly = 0.f;
            int jb = j0 + tn * 4;
#pragma unroll
            for (int u = 0; u < 4; u++) {
                int j = jb + u;
                float e = __expf(v[u] - nm);
                float gx = (float)(2 * (j & 63) - 63) * (1.f / 64.f);
                float gy = (float)(2 * (j >> 6) - 63) * (1.f / 64.f);
                ls += e; lx = fmaf(e, gx, lx); ly = fmaf(e, gy, ly);
            }
#pragma unroll
            for (int o = 16; o > 0; o >>= 1) {
                ls += __shfl_xor_sync(0xffffffffu, ls, o);
                lx += __shfl_xor_sync(0xffffffffu, lx, o);
                ly += __shfl_xor_sync(0xffffffffu, ly, o);
            }
            float sc = __expf(m[r] - nm);
            s[r]  = s[r]  * sc + ls;
            sx[r] = sx[r] * sc + lx;
            sy[r] = sy[r] * sc + ly;
            m[r]  = nm;
        }
    }

    if (tn == 0) {
#pragma unroll
        for (int r = 0; r < 4; r++) {
            int p = p0 + tm * 4 + r;
            warp[(b * 2 + 0) * HWC + p] = sx[r] / s[r];
            warp[(b * 2 + 1) * HWC + p] = sy[r] / s[r];
        }
    }
}

// ---------------------------------------------------------------------------
// Kernel 2: grid-sample feats1 at warp + concat [feats0 | warped1 | warp]
// out channels = 2C+2.  warp layout: [b][0][HW],[b][1][HW] with batch stride.
// ---------------------------------------------------------------------------
__global__ void sample_concat_kernel(
    const float* __restrict__ f0, const float* __restrict__ f1,
    const float* __restrict__ warp, int warp_bstride,
    float* __restrict__ out, int C, int H, int W)
{
    int idx = blockIdx.x * blockDim.x + threadIdx.x;
    int HW = H * W;
    if (idx >= B_ * HW) return;
    int b = idx / HW, p = idx - b * HW;

    float wx = warp[b * warp_bstride + p];
    float wy = warp[b * warp_bstride + HW + p];
    float x = (wx + 1.f) * (W * 0.5f) - 0.5f;
    float y = (wy + 1.f) * (H * 0.5f) - 0.5f;
    float x0f = floorf(x), y0f = floorf(y);
    float fx = x - x0f, fy = y - y0f;
    int x0 = (int)x0f, y0 = (int)y0f;
    int x1 = x0 + 1, y1 = y0 + 1;
    bool vx0 = (x0 >= 0 && x0 < W), vx1 = (x1 >= 0 && x1 < W);
    bool vy0 = (y0 >= 0 && y0 < H), vy1 = (y1 >= 0 && y1 < H);
    float w00 = (vx0 && vy0) ? (1.f - fx) * (1.f - fy) : 0.f;
    float w01 = (vx1 && vy0) ? fx * (1.f - fy) : 0.f;
    float w10 = (vx0 && vy1) ? (1.f - fx) * fy : 0.f;
    float w11 = (vx1 && vy1) ? fx * fy : 0.f;
    int x0c = min(max(x0, 0), W - 1), x1c = min(max(x1, 0), W - 1);
    int y0c = min(max(y0, 0), H - 1), y1c = min(max(y1, 0), H - 1);
    int i00 = y0c * W + x0c, i01 = y0c * W + x1c;
    int i10 = y1c * W + x0c, i11 = y1c * W + x1c;

    const float* f0b = f0 + (long)b * C * HW;
    const float* f1b = f1 + (long)b * C * HW;
    int outC = 2 * C + 2;
    float* ob = out + (long)b * outC * HW;

    for (int c = 0; c < C; c++) {
        const float* pl = f1b + c * HW;
        float v = w00 * pl[i00] + w01 * pl[i01] + w10 * pl[i10] + w11 * pl[i11];
        ob[(C + c) * HW + p] = v;
        ob[c * HW + p] = f0b[c * HW + p];
    }
    ob[(2 * C) * HW + p]     = wx;
    ob[(2 * C + 1) * HW + p] = wy;
}

// ---------------------------------------------------------------------------
// Kernel 3: direct 3x3 SAME conv, NCHW, fp32.
//  - input BN(scale,shift)+ReLU applied on the fly during smem load (or identity)
//  - per-block deterministic partial sum/sumsq per channel for next BN
//  Block: 64 output channels x 1 row x full width.  256 thr = 16 co-grp x 16 w-grp.
//  Thread micro-tile: 4 co x (W/16) w.  Weights staged as [ci][k][co] for LDS.128.
// ---------------------------------------------------------------------------
template <int W_>
__global__ __launch_bounds__(256) void conv3x3_kernel(
    const float* __restrict__ in, const float* __restrict__ wgt,
    const float* __restrict__ bnscale, const float* __restrict__ bnshift,
    float* __restrict__ out, float* __restrict__ psum, float* __restrict__ psq,
    int CI, int CO, int H)
{
    const int WPT = W_ / 16;
    __shared__ float in_s[4][3][W_ + 2];
    __shared__ __align__(16) float wt_s[4][9][64];
    __shared__ float2 red[64][17];

    const int cob = blockIdx.x * 64;
    const int h   = blockIdx.y;
    const int b   = blockIdx.z;
    const int tid = threadIdx.x;
    const int cog = tid >> 4;
    const int wg  = tid & 15;

    // weight-stage mapping: one (ci,co) pair per thread, 9 contiguous gmem floats
    const int w_ci = tid >> 6;      // 0..3
    const int w_co = tid & 63;      // 0..63

    float acc[4][WPT];
#pragma unroll
    for (int i = 0; i < 4; i++)
#pragma unroll
        for (int u = 0; u < WPT; u++) acc[i][u] = 0.f;

    const int nch = (CI + 3) >> 2;
    for (int ch = 0; ch < nch; ch++) {
        const int ci0 = ch * 4;
        __syncthreads();
        const int RW = W_ + 2;
        for (int e = tid; e < 4 * 3 * RW; e += 256) {
            int ci = e / (3 * RW);
            int rem = e - ci * (3 * RW);
            int r = rem / RW;
            int colp = rem - r * RW;
            int col = colp - 1;
            int row = h + r - 1;
            int cig = ci0 + ci;
            float v = 0.f;
            if (cig < CI && (unsigned)row < (unsigned)H && (unsigned)col < (unsigned)W_) {
                v = in[(((long)b * CI + cig) * H + row) * W_ + col];
                if (bnscale) v = fmaxf(fmaf(v, bnscale[cig], bnshift[cig]), 0.f);
            }
            in_s[ci][r][colp] = v;
        }
        {
            int cig = ci0 + w_ci;
            if (cig < CI) {
                const float* wp = wgt + (((long)(cob + w_co)) * CI + cig) * 9;
#pragma unroll
                for (int k = 0; k < 9; k++) wt_s[w_ci][k][w_co] = wp[k];
            } else {
#pragma unroll
                for (int k = 0; k < 9; k++) wt_s[w_ci][k][w_co] = 0.f;
            }
        }
        __syncthreads();

#pragma unroll
        for (int ci = 0; ci < 4; ci++) {
            float xr[3][WPT + 2];
#pragma unroll
            for (int r = 0; r < 3; r++)
#pragma unroll
                for (int u = 0; u < WPT + 2; u++)
                    xr[r][u] = in_s[ci][r][wg * WPT + u];
#pragma unroll
            for (int k = 0; k < 9; k++) {
                const int kh = k / 3, kw = k - kh * 3;
                float4 wv = *(const float4*)&wt_s[ci][k][cog * 4];
#pragma unroll
                for (int u = 0; u < WPT; u++) {
                    float xv = xr[kh][u + kw];
                    acc[0][u] = fmaf(wv.x, xv, acc[0][u]);
                    acc[1][u] = fmaf(wv.y, xv, acc[1][u]);
                    acc[2][u] = fmaf(wv.z, xv, acc[2][u]);
                    acc[3][u] = fmaf(wv.w, xv, acc[3][u]);
                }
            }
        }
    }

#pragma unroll
    for (int i = 0; i < 4; i++) {
        int co = cob + cog * 4 + i;
        float* op = out + (((long)b * CO + co) * H + h) * W_ + wg * WPT;
#pragma unroll
        for (int u = 0; u < WPT; u++) op[u] = acc[i][u];
    }

    if (psum) {
        const int NB  = gridDim.z * H;
        const int blk = b * H + h;
        __syncthreads();
#pragma unroll
        for (int i = 0; i < 4; i++) {
            float sv = 0.f, sq = 0.f;
#pragma unroll
            for (int u = 0; u < WPT; u++) {
                sv += acc[i][u];
                sq = fmaf(acc[i][u], acc[i][u], sq);
            }
            red[cog * 4 + i][wg] = make_float2(sv, sq);
        }
        __syncthreads();
        if (tid < 64) {
            float sv = 0.f, sq = 0.f;
            for (int w = 0; w < 16; w++) { sv += red[tid][w].x; sq += red[tid][w].y; }
            psum[(cob + tid) * NB + blk] = sv;
            psq [(cob + tid) * NB + blk] = sq;
        }
    }
}

// ---------------------------------------------------------------------------
// BN finalize: one block per channel, 256-thread deterministic tree reduction.
// ---------------------------------------------------------------------------
__global__ __launch_bounds__(256) void bn_finalize_kernel(
    const float* __restrict__ psum, const float* __restrict__ psq,
    float* __restrict__ scale, float* __restrict__ shift,
    int NB, float invN)
{
    __shared__ float ss[256], qq[256];
    const int co  = blockIdx.x;
    const int tid = threadIdx.x;
    float s = 0.f, q = 0.f;
    for (int i = tid; i < NB; i += 256) {
        s += psum[co * NB + i];
        q += psq [co * NB + i];
    }
    ss[tid] = s; qq[tid] = q;
    __syncthreads();
#pragma unroll
    for (int o = 128; o > 0; o >>= 1) {
        if (tid < o) { ss[tid] += ss[tid + o]; qq[tid] += qq[tid + o]; }
        __syncthreads();
    }
    if (tid == 0) {
        float mn  = ss[0] * invN;
        float var = fmaxf(qq[0] * invN - mn * mn, 0.f);
        float rstd = rsqrtf(var + 1e-5f);
        scale[co] = rstd;
        shift[co] = -mn * rstd;
    }
}

// ---------------------------------------------------------------------------
// 1x1 head: out = base + b5 + W5 @ relu(bn(z)).  base_ch channels of base used.
// ---------------------------------------------------------------------------
__global__ __launch_bounds__(256) void head1x1_kernel(
    const float* __restrict__ z, const float* __restrict__ scale,
    const float* __restrict__ shift, const float* __restrict__ w5,
    const float* __restrict__ b5, const float* __restrict__ base,
    int base_ch, int base_bstride, float* __restrict__ out, int CI, int HW)
{
    __shared__ float ws[3 * 256];
    __shared__ float sc[256], sh[256];
    int tid = threadIdx.x;
    for (int e = tid; e < 3 * CI; e += 256) ws[e] = w5[e];
    for (int e = tid; e < CI; e += 256) { sc[e] = scale[e]; sh[e] = shift[e]; }
    __syncthreads();

    int idx = blockIdx.x * 256 + tid;
    if (idx >= B_ * HW) return;
    int b = idx / HW, p = idx - b * HW;

    float a0 = b5[0], a1 = b5[1], a2 = b5[2];
    const float* zb = z + (long)b * CI * HW + p;
    for (int ci = 0; ci < CI; ci++) {
        float v = fmaxf(fmaf(zb[(long)ci * HW], sc[ci], sh[ci]), 0.f);
        a0 = fmaf(ws[ci], v, a0);
        a1 = fmaf(ws[CI + ci], v, a1);
        a2 = fmaf(ws[2 * CI + ci], v, a2);
    }
    const float* bb = base + (long)b * base_bstride;
    out[((long)b * 3 + 0) * HW + p] = a0 + bb[p];
    out[((long)b * 3 + 1) * HW + p] = a1 + bb[HW + p];
    out[((long)b * 3 + 2) * HW + p] = a2 + (base_ch > 2 ? bb[2 * HW + p] : 0.f);
}

// ---------------------------------------------------------------------------
// jax bilinear 2x upsample 64->128 (half-pixel centers, edge-renorm == clamp)
// ---------------------------------------------------------------------------
__global__ void upsample_kernel(const float* __restrict__ cm, float* __restrict__ up)
{
    int idx = blockIdx.x * blockDim.x + threadIdx.x;
    if (idx >= B_ * 3 * HWF) return;
    int wo = idx & 127;
    int ho = (idx >> 7) & 127;
    int cb = idx >> 14;   // b*3 + c
    float fx = wo * 0.5f - 0.25f;
    float fy = ho * 0.5f - 0.25f;
    float x0f = floorf(fx), y0f = floorf(fy);
    float tx = fx - x0f, ty = fy - y0f;
    int x0 = (int)x0f, y0 = (int)y0f;
    int x0c = max(x0, 0), x1c = min(x0 + 1, 63);
    int y0c = max(y0, 0), y1c = min(y0 + 1, 63);
    const float* pl = cm + (long)cb * HWC;
    float v = (1.f - tx) * (1.f - ty) * pl[y0c * 64 + x0c]
            + tx * (1.f - ty) * pl[y0c * 64 + x1c]
            + (1.f - tx) * ty * pl[y1c * 64 + x0c]
            + tx * ty * pl[y1c * 64 + x1c];
    up[idx] = v;
}

// ---------------------------------------------------------------------------
extern "C" void kernel_launch(void* const* d_in, const int* in_sizes, int n_in,
                              void* d_out, int out_size)
{
    const float* f0c = (const float*)d_in[0];
    const float* f1c = (const float*)d_in[1];
    const float* f0f = (const float*)d_in[2];
    const float* f1f = (const float*)d_in[3];
    const float* cw1 = (const float*)d_in[4];
    const float* cw2 = (const float*)d_in[5];
    const float* cw3 = (const float*)d_in[6];
    const float* cw4 = (const float*)d_in[7];
    const float* cw5 = (const float*)d_in[8];
    const float* cb5 = (const float*)d_in[9];
    const float* fw1 = (const float*)d_in[10];
    const float* fw2 = (const float*)d_in[11];
    const float* fw3 = (const float*)d_in[12];
    const float* fw4 = (const float*)d_in[13];
    const float* fw5 = (const float*)d_in[14];
    const float* fb5 = (const float*)d_in[15];
    float* out = (float*)d_out;

    float *warp, *xin, *za, *zb, *up, *yin, *ps, *pq, *scale, *shift;
    cudaGetSymbolAddress((void**)&warp,  g_warp);
    cudaGetSymbolAddress((void**)&xin,   g_xin);
    cudaGetSymbolAddress((void**)&za,    g_za);
    cudaGetSymbolAddress((void**)&zb,    g_zb);
    cudaGetSymbolAddress((void**)&up,    g_up);
    cudaGetSymbolAddress((void**)&yin,   g_yin);
    cudaGetSymbolAddress((void**)&ps,    g_ps);
    cudaGetSymbolAddress((void**)&pq,    g_pq);
    cudaGetSymbolAddress((void**)&scale, g_scale);
    cudaGetSymbolAddress((void**)&shift, g_shift);

    // ---- coarse stage ----
    corr_warp_kernel<<<dim3(HWC / 32, B_), 256>>>(f0c, f1c, warp);
    sample_concat_kernel<<<(B_ * HWC + 255) / 256, 256>>>(f0c, f1c, warp, 2 * HWC,
                                                          xin, 64, 64, 64);
    const float invNc = 1.f / (B_ * HWC);
    conv3x3_kernel<64><<<dim3(4, 64, B_), 256>>>(xin, cw1, nullptr, nullptr,
                                                 za, ps, pq, 130, 256, 64);
    bn_finalize_kernel<<<256, 256>>>(ps, pq, scale, shift, B_ * 64, invNc);
    conv3x3_kernel<64><<<dim3(4, 64, B_), 256>>>(za, cw2, scale, shift,
                                                 zb, ps, pq, 256, 256, 64);
    bn_finalize_kernel<<<256, 256>>>(ps, pq, scale, shift, B_ * 64, invNc);
    conv3x3_kernel<64><<<dim3(4, 64, B_), 256>>>(zb, cw3, scale, shift,
                                                 za, ps, pq, 256, 256, 64);
    bn_finalize_kernel<<<256, 256>>>(ps, pq, scale, shift, B_ * 64, invNc);
    conv3x3_kernel<64><<<dim3(4, 64, B_), 256>>>(za, cw4, scale, shift,
                                                 zb, ps, pq, 256, 256, 64);
    bn_finalize_kernel<<<256, 256>>>(ps, pq, scale, shift, B_ * 64, invNc);
    head1x1_kernel<<<(B_ * HWC + 255) / 256, 256>>>(zb, scale, shift, cw5, cb5,
                                                    warp, 2, 2 * HWC, out, 256, HWC);

    // ---- upsample + fine stage ----
    upsample_kernel<<<(B_ * 3 * HWF + 255) / 256, 256>>>(out, up);
    sample_concat_kernel<<<(B_ * HWF + 255) / 256, 256>>>(f0f, f1f, up, 3 * HWF,
                                                          yin, 24, 128, 128);
    const float invNf = 1.f / (B_ * HWF);
    conv3x3_kernel<128><<<dim3(1, 128, B_), 256>>>(yin, fw1, nullptr, nullptr,
                                                   za, ps, pq, 50, 64, 128);
    bn_finalize_kernel<<<64, 256>>>(ps, pq, scale, shift, B_ * 128, invNf);
    conv3x3_kernel<128><<<dim3(1, 128, B_), 256>>>(za, fw2, scale, shift,
                                                   zb, ps, pq, 64, 64, 128);
    bn_finalize_kernel<<<64, 256>>>(ps, pq, scale, shift, B_ * 128, invNf);
    conv3x3_kernel<128><<<dim3(1, 128, B_), 256>>>(zb, fw3, scale, shift,
                                                   za, ps, pq, 64, 64, 128);
    bn_finalize_kernel<<<64, 256>>>(ps, pq, scale, shift, B_ * 128, invNf);
    conv3x3_kernel<128><<<dim3(1, 128, B_), 256>>>(za, fw4, scale, shift,
                                                   zb, ps, pq, 64, 64, 128);
    bn_finalize_kernel<<<64, 256>>>(ps, pq, scale, shift, B_ * 128, invNf);
    head1x1_kernel<<<(B_ * HWF + 255) / 256, 256>>>(zb, scale, shift, fw5, fb5,
                                                    up, 3, 3 * HWF,
                                                    out + B_ * 3 * HWC, 64, HWF);
}